// round 9
// baseline (speedup 1.0000x reference)
#include <cuda_runtime.h>
#include <cuda_bf16.h>
#include <math.h>

#define KS    11
#define HALO  5
#define IMG   512
#define TW    128            // tile width (outputs)
#define TH    32             // tile height (outputs)
#define TSTR  193            // smem row stride; 193 mod 32 = 1 -> conflict-free
#define NTHR  192            // 6 warps

__device__ float g_w[KS];

__global__ void gb_weights_kernel(const float* __restrict__ sigma) {
    if (threadIdx.x == 0) {
        float s = fabsf(sigma[0]) + 1e-6f;
        float inv2s2 = 1.0f / (2.0f * s * s);
        float w[KS];
        float sum = 0.0f;
        #pragma unroll
        for (int i = 0; i < KS; i++) {
            float r = (float)i - (float)(KS - 1) * 0.5f;
            w[i] = expf(-(r * r) * inv2s2);
            sum += w[i];
        }
        float inv = 1.0f / sum;
        #pragma unroll
        for (int i = 0; i < KS; i++) g_w[i] = w[i] * inv;
    }
}

__device__ __forceinline__ int reflect_idx(int i) {
    i = (i < 0) ? -i : i;
    return (i > IMG - 1) ? 2 * (IMG - 1) - i : i;
}

__global__ void __launch_bounds__(NTHR)
gb_blur_kernel(const float* __restrict__ x, float* __restrict__ out) {
    __shared__ float tmp[TH * TSTR];   // 32 x 193 floats = 24.7 KB

    const int tid   = threadIdx.x;
    const int plane = blockIdx.z;
    const int x0    = blockIdx.x * TW;
    const int y0    = blockIdx.y * TH;

    const float* __restrict__ base = x + (size_t)plane * (IMG * IMG);

    float w[KS];
    #pragma unroll
    for (int k = 0; k < KS; k++) w[k] = __ldg(&g_w[k]);

    // ---------------- P1: vertical pass, global -> smem ----------------
    // One column per thread (192 cols, [x0-32, x0+160), 128B-aligned LDGs;
    // warp lanes read consecutive addresses -> 1 wavefront per LDG).
    // Sliding 11-register window keeps register pressure low.
    {
        const int cx = reflect_idx(x0 - 32 + tid);
        const float* __restrict__ col = base + cx;

        float win[KS];
        #pragma unroll
        for (int i = 0; i < KS - 1; i++) {
            int y = reflect_idx(y0 - HALO + i);
            win[i] = __ldg(col + y * IMG);
        }

        #pragma unroll
        for (int r = 0; r < TH; r++) {
            int y = reflect_idx(y0 + HALO + r);
            win[(r + KS - 1) % KS] = __ldg(col + y * IMG);

            float acc = 0.0f;
            #pragma unroll
            for (int k = 0; k < KS; k++)
                acc = fmaf(win[(r + k) % KS], w[k], acc);
            tmp[r * TSTR + tid] = acc;
        }
    }
    __syncthreads();

    // ---------------- P2: horizontal pass, smem -> global ----------------
    // 32 patches of 4 rows x 32 cols, distributed over 6 warps.
    // Lane -> (row = lane>>3, col4 = lane&7): LDS bank = C + row + 4*col4
    // (stride 193 ≡ 1 mod 32) -> 32 distinct banks, conflict-free.
    // Each lane: 14-float window -> 4 outputs -> one float4 STG
    // (8 lanes per 128B line, fully coalesced).
    const int wp   = tid >> 5;
    const int lane = tid & 31;
    const int lrow = lane >> 3;          // 0..3
    const int lc4  = (lane & 7) * 4;     // 0,4,...,28

    float* __restrict__ oplane = out + (size_t)plane * (IMG * IMG);

    #pragma unroll
    for (int it = 0; it < 6; it++) {
        const int p = wp + it * 6;       // 0..35; skip p >= 32
        if (p < 32) {
            const int rg  = p >> 2;      // row group 0..7
            const int cs  = p & 3;       // col strip 0..3
            const int row = rg * 4 + lrow;
            const int colbase = cs * 32 + lc4;      // 0..124, multiple of 4

            const float* __restrict__ trow = tmp + row * TSTR + (32 - HALO) + colbase;

            float win[KS + 3];
            #pragma unroll
            for (int i = 0; i < KS + 3; i++) win[i] = trow[i];

            float a0 = 0.f, a1 = 0.f, a2 = 0.f, a3 = 0.f;
            #pragma unroll
            for (int k = 0; k < KS; k++) {
                a0 = fmaf(win[k    ], w[k], a0);
                a1 = fmaf(win[k + 1], w[k], a1);
                a2 = fmaf(win[k + 2], w[k], a2);
                a3 = fmaf(win[k + 3], w[k], a3);
            }

            float4* __restrict__ o = reinterpret_cast<float4*>(
                oplane + (size_t)(y0 + row) * IMG + x0 + colbase);
            *o = make_float4(a0, a1, a2, a3);
        }
    }
}

extern "C" void kernel_launch(void* const* d_in, const int* in_sizes, int n_in,
                              void* d_out, int out_size) {
    const float* x     = (const float*)d_in[0];   // (16, 64, 512, 512) fp32
    const float* sigma = (const float*)d_in[1];   // (1,) fp32
    float* out = (float*)d_out;

    gb_weights_kernel<<<1, 32>>>(sigma);

    dim3 grid(IMG / TW, IMG / TH, 16 * 64);       // (4, 16, 1024)
    gb_blur_kernel<<<grid, NTHR>>>(x, out);
}